// round 1
// baseline (speedup 1.0000x reference)
#include <cuda_runtime.h>
#include <cuda_bf16.h>

// ---------------------------------------------------------------------------
// BottomUpHTMM — complete 4-ary tree, depth 7.
// Static tree structure: limits = {0,1,5,21,85,341,1365,5461,21845}
// G=16 generators, C=8 states, L=4 children, M=256 labels.
// Layout of all state arrays: [node][g][c], c fastest (32B per (node,g)).
// ---------------------------------------------------------------------------

#define T_SIZE   21845
#define N_INT    5461          // internal nodes (lim[-2])
#define G_N      16
#define C_N      8
#define L_N      4
#define M_N      256
#define GC       128           // G*C

// device scratch (static allocation is allowed)
__device__ float g_prior[T_SIZE * GC];
__device__ float g_beta [T_SIZE * GC];
__device__ float g_sbeta[N_INT  * GC];
__device__ float g_eps  [T_SIZE * GC];

// small tables
__device__ float g_asp [G_N * C_N * L_N * C_N];   // a_sp[g][i][l][j]
__device__ float g_loga[G_N * C_N * L_N * C_N];   // log(sm_a)[g][i][l][j]
__device__ float g_bt  [G_N * M_N * C_N];         // sm_b  [g][m][c]
__device__ float g_lbt [G_N * M_N * C_N];         // log sm_b
__device__ float g_pit [G_N * L_N * C_N];         // sm_pi [g][pos][c]
__device__ float g_lpit[G_N * L_N * C_N];
__device__ float g_lsp [G_N * L_N];               // log sm_sp

// partial-sum buffer: down kernels + final kernel write one slot of 16 per block
#define DOWN_SLOT0  0     // grid 1
#define DOWN_SLOT1  1     // grid 4
#define DOWN_SLOT2  5     // grid 16
#define DOWN_SLOT3  21    // grid 64
#define DOWN_SLOT4  85    // grid 256
#define DOWN_SLOT5  341   // grid 296
#define DOWN_SLOT6  637   // grid 296
#define FIN_BASE    933   // grid 296
#define TOTAL_SLOTS 1229
__device__ float g_partial[TOTAL_SLOTS * 16];

// ---------------------------------------------------------------------------
// prep: softmaxes + logs into tables.
// block 0: sp / pi / a.   blocks 1..16: b rows for g = blockIdx-1.
// ---------------------------------------------------------------------------
__global__ void prep_kernel(const float* __restrict__ a,
                            const float* __restrict__ b,
                            const float* __restrict__ pi,
                            const float* __restrict__ sp)
{
    const int t = threadIdx.x;           // 256 threads
    if (blockIdx.x == 0) {
        __shared__ float s_sp[G_N * L_N];
        // sm_sp: 16 softmaxes over 4
        if (t < G_N) {
            float v[L_N]; float mx = -1e30f;
            #pragma unroll
            for (int l = 0; l < L_N; l++) { v[l] = sp[t*L_N + l]; mx = fmaxf(mx, v[l]); }
            float s = 0.f;
            #pragma unroll
            for (int l = 0; l < L_N; l++) { v[l] = expf(v[l] - mx); s += v[l]; }
            float inv = 1.f / s;
            #pragma unroll
            for (int l = 0; l < L_N; l++) {
                float sm = v[l] * inv;
                s_sp[t*L_N + l]  = sm;
                g_lsp[t*L_N + l] = logf(sm);
            }
        }
        // sm_pi: 64 (g,l) groups, softmax over c (stride L_N)
        if (t < G_N * L_N) {
            int g = t >> 2, l = t & 3;
            float v[C_N]; float mx = -1e30f;
            #pragma unroll
            for (int c = 0; c < C_N; c++) { v[c] = pi[g*C_N*L_N + c*L_N + l]; mx = fmaxf(mx, v[c]); }
            float s = 0.f;
            #pragma unroll
            for (int c = 0; c < C_N; c++) { v[c] = expf(v[c] - mx); s += v[c]; }
            float inv = 1.f / s, ls = logf(s);
            #pragma unroll
            for (int c = 0; c < C_N; c++) {
                g_pit [g*32 + l*C_N + c] = v[c] * inv;
                g_lpit[g*32 + l*C_N + c] = logf(v[c]) - ls;   // = (x-mx) - log(sum)
            }
        }
        __syncthreads();
        // sm_a: 512 (g,j,l) groups, softmax over i (stride 32)
        for (int grp = t; grp < 512; grp += 256) {
            int g = grp >> 5, j = (grp >> 2) & 7, l = grp & 3;
            float v[C_N]; float mx = -1e30f;
            #pragma unroll
            for (int i = 0; i < C_N; i++) {
                v[i] = a[g*256 + i*32 + j*4 + l];
                mx = fmaxf(mx, v[i]);
            }
            float s = 0.f;
            #pragma unroll
            for (int i = 0; i < C_N; i++) { v[i] = expf(v[i] - mx); s += v[i]; }
            float inv = 1.f / s, ls = logf(s);
            float spv = s_sp[g*L_N + l];
            #pragma unroll
            for (int i = 0; i < C_N; i++) {
                int idx = ((g*8 + i)*4 + l)*8 + j;
                float sm = v[i] * inv;
                g_asp [idx] = sm * spv;
                g_loga[idx] = logf(v[i]) - ls;
            }
        }
    } else {
        // b: one block per g, warp per c. softmax over m (contiguous).
        int g = blockIdx.x - 1;
        int w = t >> 5, lane = t & 31;   // 8 warps -> c = w
        const float* bp = b + (g*8 + w) * 256;
        float mx = -1e30f;
        for (int m = lane; m < 256; m += 32) mx = fmaxf(mx, bp[m]);
        #pragma unroll
        for (int o = 16; o; o >>= 1) mx = fmaxf(mx, __shfl_xor_sync(0xffffffffu, mx, o));
        float s = 0.f;
        for (int m = lane; m < 256; m += 32) s += expf(bp[m] - mx);
        #pragma unroll
        for (int o = 16; o; o >>= 1) s += __shfl_xor_sync(0xffffffffu, s, o);
        float inv = 1.f / s, ls = logf(s);
        for (int m = lane; m < 256; m += 32) {
            float e = bp[m] - mx;
            g_bt [g*2048 + m*8 + w] = expf(e) * inv;
            g_lbt[g*2048 + m*8 + w] = e - ls;
        }
    }
}

// ---------------------------------------------------------------------------
// leaves: nodes 5461..21844
// ---------------------------------------------------------------------------
__global__ void leaf_kernel(const int* __restrict__ tn)
{
    int idx = blockIdx.x * blockDim.x + threadIdx.x;
    if (idx >= 16384 * G_N) return;
    int u = N_INT + (idx >> 4);
    int g = idx & 15;
    int lab = tn[u * 7];
    int pos = (u - 1) & 3;
    const float4* pp = (const float4*)&g_pit[g*32 + pos*8];
    const float4* bb = (const float4*)&g_bt [g*2048 + lab*8];
    float4 p0 = pp[0], p1 = pp[1], e0 = bb[0], e1 = bb[1];
    float4 t0, t1;
    t0.x = p0.x*e0.x; t0.y = p0.y*e0.y; t0.z = p0.z*e0.z; t0.w = p0.w*e0.w;
    t1.x = p1.x*e1.x; t1.y = p1.y*e1.y; t1.z = p1.z*e1.z; t1.w = p1.w*e1.w;
    float s = t0.x+t0.y+t0.z+t0.w + t1.x+t1.y+t1.z+t1.w;
    float inv = 1.f / s;
    t0.x *= inv; t0.y *= inv; t0.z *= inv; t0.w *= inv;
    t1.x *= inv; t1.y *= inv; t1.z *= inv; t1.w *= inv;
    float4* po = (float4*)&g_prior[u*GC + g*8];
    po[0] = p0; po[1] = p1;
    float4* bo = (float4*)&g_beta[u*GC + g*8];
    bo[0] = t0; bo[1] = t1;
}

// ---------------------------------------------------------------------------
// upward: one level per launch. block = 128 threads = (g,i).
// ---------------------------------------------------------------------------
__global__ void up_kernel(const int* __restrict__ tn, int s, int n)
{
    const int tid = threadIdx.x;
    const int g = tid >> 3, i = tid & 7;
    float as[4][8];
    {
        const float4* ap = (const float4*)&g_asp[tid * 32];
        #pragma unroll
        for (int l = 0; l < 4; l++) {
            float4 x0 = ap[l*2], x1 = ap[l*2 + 1];
            as[l][0]=x0.x; as[l][1]=x0.y; as[l][2]=x0.z; as[l][3]=x0.w;
            as[l][4]=x1.x; as[l][5]=x1.y; as[l][6]=x1.z; as[l][7]=x1.w;
        }
    }
    __shared__ float s_pc[512], s_bc[512];
    for (int node = s + blockIdx.x; node < s + n; node += gridDim.x) {
        int cb = (4*node + 1) * GC;
        ((float4*)s_pc)[tid] = *(const float4*)&g_prior[cb + tid*4];
        ((float4*)s_bc)[tid] = *(const float4*)&g_beta [cb + tid*4];
        __syncthreads();
        float p = 0.f, sb = 0.f;
        #pragma unroll
        for (int l = 0; l < 4; l++) {
            const float4* pc = (const float4*)&s_pc[l*128 + g*8];
            const float4* bc = (const float4*)&s_bc[l*128 + g*8];
            float4 p0 = pc[0], p1 = pc[1], b0 = bc[0], b1 = bc[1];
            p  += as[l][0]*p0.x + as[l][1]*p0.y + as[l][2]*p0.z + as[l][3]*p0.w
                + as[l][4]*p1.x + as[l][5]*p1.y + as[l][6]*p1.z + as[l][7]*p1.w;
            sb += as[l][0]*b0.x + as[l][1]*b0.y + as[l][2]*b0.z + as[l][3]*b0.w
                + as[l][4]*b1.x + as[l][5]*b1.y + as[l][6]*b1.z + as[l][7]*b1.w;
        }
        int lab = tn[node * 7];
        float emis = g_bt[g*2048 + lab*8 + i];
        float tmp = emis * sb;
        float ts = tmp;
        ts += __shfl_xor_sync(0xffffffffu, ts, 4);
        ts += __shfl_xor_sync(0xffffffffu, ts, 2);
        ts += __shfl_xor_sync(0xffffffffu, ts, 1);
        float bv = tmp / ts;
        g_prior[node*GC + tid] = p;
        g_sbeta[node*GC + tid] = sb;
        g_beta [node*GC + tid] = bv;
        __syncthreads();
    }
}

// ---------------------------------------------------------------------------
// downward: one level per launch. block = 128 threads = (g,i).
// accumulates a_lh + sp_lh contributions into g_partial[slotBase+blockIdx].
// ---------------------------------------------------------------------------
__global__ void down_kernel(int s, int n, int isRoot, int slotBase)
{
    const int tid = threadIdx.x;
    const int g = tid >> 3, i = tid & 7;
    (void)i;
    float as[4][8], asla[4][8];
    {
        const float4* ap = (const float4*)&g_asp [tid * 32];
        const float4* lp = (const float4*)&g_loga[tid * 32];
        #pragma unroll
        for (int l = 0; l < 4; l++) {
            float4 x0 = ap[l*2], x1 = ap[l*2+1];
            float4 y0 = lp[l*2], y1 = lp[l*2+1];
            as[l][0]=x0.x; as[l][1]=x0.y; as[l][2]=x0.z; as[l][3]=x0.w;
            as[l][4]=x1.x; as[l][5]=x1.y; as[l][6]=x1.z; as[l][7]=x1.w;
            asla[l][0]=x0.x*y0.x; asla[l][1]=x0.y*y0.y; asla[l][2]=x0.z*y0.z; asla[l][3]=x0.w*y0.w;
            asla[l][4]=x1.x*y1.x; asla[l][5]=x1.y*y1.y; asla[l][6]=x1.z*y1.z; asla[l][7]=x1.w*y1.w;
        }
    }
    float lsp[4];
    #pragma unroll
    for (int l = 0; l < 4; l++) lsp[l] = g_lsp[g*4 + l];

    __shared__ float s_bc[512];
    __shared__ float s_red[16];
    float acc = 0.f;

    for (int node = s + blockIdx.x; node < s + n; node += gridDim.x) {
        float epsv;
        if (isRoot) { epsv = g_beta[tid]; g_eps[tid] = epsv; }
        else        { epsv = g_eps[node*GC + tid]; }
        float pe = epsv / g_sbeta[node*GC + tid];

        int cb = (4*node + 1) * GC;
        ((float4*)s_bc)[tid] = *(const float4*)&g_beta[cb + tid*4];
        __syncthreads();
        #pragma unroll
        for (int l = 0; l < 4; l++) {
            const float4* bc = (const float4*)&s_bc[l*128 + g*8];
            float4 b0 = bc[0], b1 = bc[1];
            float ce = as[l][0]*b0.x + as[l][1]*b0.y + as[l][2]*b0.z + as[l][3]*b0.w
                     + as[l][4]*b1.x + as[l][5]*b1.y + as[l][6]*b1.z + as[l][7]*b1.w;
            float ca = asla[l][0]*b0.x + asla[l][1]*b0.y + asla[l][2]*b0.z + asla[l][3]*b0.w
                     + asla[l][4]*b1.x + asla[l][5]*b1.y + asla[l][6]*b1.z + asla[l][7]*b1.w;
            ce *= pe;
            g_eps[cb + l*128 + tid] = ce;           // eps of child (4*node+1+l)
            acc += pe * ca + lsp[l] * ce;           // a_lh + sp_lh terms
        }
        __syncthreads();
    }
    // per-g reduction
    acc += __shfl_xor_sync(0xffffffffu, acc, 4);
    acc += __shfl_xor_sync(0xffffffffu, acc, 2);
    acc += __shfl_xor_sync(0xffffffffu, acc, 1);
    if ((tid & 7) == 0) s_red[g] = acc;
    __syncthreads();
    if (tid < 16) g_partial[(slotBase + blockIdx.x)*16 + tid] = s_red[tid];
}

// ---------------------------------------------------------------------------
// final: b_lh over all nodes + pi_lh over leaves
// ---------------------------------------------------------------------------
__global__ void final_kernel(const int* __restrict__ tn)
{
    const int tid = threadIdx.x;     // 256
    __shared__ float sacc[16];
    if (tid < 16) sacc[tid] = 0.f;
    __syncthreads();
    float acc = 0.f;
    const int total = T_SIZE * G_N;
    for (int idx = blockIdx.x * blockDim.x + tid; idx < total; idx += gridDim.x * blockDim.x) {
        int u = idx >> 4;
        int g = idx & 15;
        const float4* e = (const float4*)&g_eps[u*GC + g*8];
        float4 e0 = e[0], e1 = e[1];
        int lab = tn[u * 7];
        const float4* lb = (const float4*)&g_lbt[g*2048 + lab*8];
        float4 l0 = lb[0], l1 = lb[1];
        acc += e0.x*l0.x + e0.y*l0.y + e0.z*l0.z + e0.w*l0.w
             + e1.x*l1.x + e1.y*l1.y + e1.z*l1.z + e1.w*l1.w;
        if (u >= N_INT) {
            int pos = (u - 1) & 3;
            const float4* lp = (const float4*)&g_lpit[g*32 + pos*8];
            float4 q0 = lp[0], q1 = lp[1];
            acc += e0.x*q0.x + e0.y*q0.y + e0.z*q0.z + e0.w*q0.w
                 + e1.x*q1.x + e1.y*q1.y + e1.z*q1.z + e1.w*q1.w;
        }
    }
    acc += __shfl_xor_sync(0xffffffffu, acc, 16);
    if ((tid & 31) < 16) atomicAdd(&sacc[tid & 15], acc);
    __syncthreads();
    if (tid < 16) g_partial[(FIN_BASE + blockIdx.x)*16 + tid] = sacc[tid];
}

// ---------------------------------------------------------------------------
// combine partials -> d_out
// ---------------------------------------------------------------------------
__global__ void combine_kernel(float* __restrict__ out)
{
    const int tid = threadIdx.x;    // 256
    __shared__ float sacc[16];
    if (tid < 16) sacc[tid] = 0.f;
    __syncthreads();
    float acc = 0.f;
    for (int f = tid; f < TOTAL_SLOTS * 16; f += 256) acc += g_partial[f];
    atomicAdd(&sacc[tid & 15], acc);
    __syncthreads();
    if (tid < 16) out[tid] = sacc[tid];
}

// ---------------------------------------------------------------------------
extern "C" void kernel_launch(void* const* d_in, const int* in_sizes, int n_in,
                              void* d_out, int out_size)
{
    const int*   t_nodes = (const int*)  d_in[0];
    const float* a       = (const float*)d_in[2];
    const float* b       = (const float*)d_in[3];
    const float* pi      = (const float*)d_in[4];
    const float* sp      = (const float*)d_in[5];
    float* out = (float*)d_out;

    static const int lim[9] = {0, 1, 5, 21, 85, 341, 1365, 5461, 21845};
    static const int down_base[7] = {DOWN_SLOT0, DOWN_SLOT1, DOWN_SLOT2, DOWN_SLOT3,
                                     DOWN_SLOT4, DOWN_SLOT5, DOWN_SLOT6};

    prep_kernel<<<17, 256>>>(a, b, pi, sp);
    leaf_kernel<<<(16384 * 16 + 255) / 256, 256>>>(t_nodes);

    for (int lev = 6; lev >= 0; lev--) {
        int s = lim[lev], n = lim[lev + 1] - lim[lev];
        int grid = n < 448 ? n : 448;
        up_kernel<<<grid, 128>>>(t_nodes, s, n);
    }
    for (int lev = 0; lev <= 6; lev++) {
        int s = lim[lev], n = lim[lev + 1] - lim[lev];
        int grid = n < 296 ? n : 296;
        down_kernel<<<grid, 128>>>(s, n, lev == 0 ? 1 : 0, down_base[lev]);
    }
    final_kernel<<<296, 256>>>(t_nodes);
    combine_kernel<<<1, 256>>>(out);
}